// round 16
// baseline (speedup 1.0000x reference)
#include <cuda_runtime.h>
#include <math.h>

// Fixed problem shapes: N=8192 atoms, E=32768 edges (guarded for safety).
#define N_MAX   8192
#define E_MAX   32768
#define ROWCAP  32          // padded CSR row capacity; one row == one 128B cache line
#define NCELL   25
#define NCELL3  15625       // 25^3
#define CINV    0.3125f     // 1/3.2 ; cell 3.2 > max cutoff 3.168 + drift margin
#define CORG    40.0f
#define HOT_SPINS  100000000u  // hot-poll budget (~0.1s) before backoff; never trips normally
#define ABLK    128
#define ATHR    64
#define BBLK    160         // 128 bond-blocks + 32 cellcount-blocks
#define BTHR    256
#define PF      16          // sweep prefetch width: one batch covers P(deg<=16) ~ 1

// ---------------- device scratch (zero-init; restored each run by kC) -------------
__device__ int    g_cursor[N_MAX];
__device__ int    g_csr[N_MAX * ROWCAP];    // edge ids; after sweep1 (violating rows): cols
__device__ float  g_viol[N_MAX];
__device__ float  g_rad8[N_MAX];
__device__ float  g_pA[N_MAX * 3];
__device__ float  g_pB[N_MAX * 3];
__device__ float  g_pos2[N_MAX * 3];
__device__ int    g_ccount[NCELL3];
__device__ int    g_ccur[NCELL3];
__device__ int    g_coff[NCELL3 + 1];
__device__ float4 g_catom[N_MAX];
__device__ int    g_cidx[N_MAX];
__device__ float  g_l1part[ABLK];
__device__ float  g_l2part[ABLK];
__device__ float  g_l3part[1024];
__device__ int    g_barc[8];                // spin-barrier counters (kA:0-2, kB:3-4)
__device__ int    g_done;                   // kC last-block ticket

// ---------------- chemistry as branchy constants ----------------
__device__ __forceinline__ float maxval_of(int z) {
    switch (z) {
        case 6:  return 4.f; case 7:  return 3.f; case 8:  return 2.f;
        case 16: return 6.f; case 15: return 5.f;
        case 9: case 17: case 35: case 53: case 1: return 1.f;
        default: return 4.f;
    }
}
__device__ __forceinline__ float vdw_of(int z) {
    switch (z) {
        case 1:  return 1.2f;  case 6:  return 1.7f;  case 7:  return 1.55f;
        case 8:  return 1.52f; case 9:  return 1.47f; case 15: return 1.8f;
        case 16: return 1.8f;  case 17: return 1.75f; case 35: return 1.85f;
        case 53: return 1.98f; default: return 1.6f;
    }
}
__device__ __forceinline__ float bond_of(int a, int b) {
    if (a > b) { int t = a; a = b; b = t; }
    switch (a * 64 + b) {
        case 1*64+6:  return 1.09f; case 1*64+7:  return 1.01f; case 1*64+8:  return 0.96f;
        case 6*64+6:  return 1.54f; case 6*64+7:  return 1.47f; case 6*64+8:  return 1.43f;
        case 6*64+9:  return 1.35f; case 6*64+16: return 1.82f; case 6*64+17: return 1.77f;
        case 7*64+7:  return 1.45f; case 7*64+8:  return 1.40f; case 8*64+8:  return 1.48f;
        case 8*64+15: return 1.63f; case 16*64+16: return 2.05f;
        default: return 1.5f;
    }
}
__device__ __forceinline__ int cell_coord(float v) {
    int c = (int)floorf((v + CORG) * CINV);
    return min(max(c, 0), NCELL - 1);
}
__device__ __forceinline__ int cell_of(float x, float y, float z) {
    return (cell_coord(z) * NCELL + cell_coord(y)) * NCELL + cell_coord(x);
}

// ---- grid-wide barrier: HOT spin (no sleep) + bounded backoff tail ----------------
// R15 evidence: nanosleep-in-loop cost ~3us/barrier; hot spin targets ~0.5us.
__device__ __forceinline__ void gbar(int idx, int nblk) {
    __syncthreads();
    if (threadIdx.x == 0) {
        __threadfence();
        atomicAdd(&g_barc[idx], 1);
        unsigned spins = 0;
        while (*(volatile int*)&g_barc[idx] < nblk) {
            if (++spins > HOT_SPINS) {           // diagnostic tail; never trips normally
                __nanosleep(1000);
                if (spins > HOT_SPINS + 100000u) break;
            }
        }
        __threadfence();
    }
    __syncthreads();
}

// -------- fast push chain: prefetch PF neighbors, rsqrt math (validated 1.44e-7) ---
__device__ __forceinline__ void pushPF(float s, int m,
                                       const float* nx, const float* ny, const float* nz,
                                       const int* sk, float& x, float& y, float& z) {
    #pragma unroll
    for (int t = 0; t < PF; t++) {
        if (t < m && !sk[t]) {
            float dx = x - nx[t], dy = y - ny[t], dz = z - nz[t];
            float d2 = dx * dx + dy * dy + dz * dz;
            float f = s * rsqrtf(fmaxf(d2, 1e-24f));
            x += dx * f; y += dy * f; z += dz * f;
        }
    }
}

// ================= kA: fill + 3 Jacobi sweeps (128 x 64, 3 grid barriers) ==========
__global__ void __launch_bounds__(ATHR) kA(const float* __restrict__ orig,
                                           const int* __restrict__ row,
                                           const int* __restrict__ col,
                                           const int* __restrict__ types,
                                           int N, int E) {
    __shared__ float sl[ATHR];
    const int tid  = threadIdx.x;
    const int bid  = blockIdx.x;
    const int gtid = bid * ATHR + tid;          // == atom id in sweep phases
    const int GT   = ABLK * ATHR;               // 8192

    // ---- fill: padded CSR of edge ids (slot order irrelevant; sweep1 sorts) ----
    for (int e = gtid; e < E; e += GT) {
        int r = row[e];
        int p = atomicAdd(&g_cursor[r], 1);
        if (p < ROWCAP) g_csr[r * ROWCAP + p] = e;
    }
    gbar(0, ABLK);

    // ---- sweep 1: sort violating rows, viol/loss1/rad8, push ----
    {
        float lloss = 0.0f;
        int i = gtid;
        if (i < N) {
            int deg = __ldcg(&g_cursor[i]);      // written by other blocks' atomics
            int cnt = min(deg, ROWCAP);
            int z = types[i];
            float v = fmaxf((float)deg - maxval_of(z), 0.0f);
            g_viol[i] = v;
            lloss = v * v;
            g_rad8[i] = vdw_of(z) * 0.8f;
            float x = orig[3*i], y = orig[3*i+1], zz = orig[3*i+2];
            if (v > 0.0f) {
                int base = i * ROWCAP;
                int eid[ROWCAP];
                for (int k = 0; k < cnt; k++) eid[k] = __ldcg(&g_csr[base + k]);
                for (int a = 1; a < cnt; a++) {  // stable = ascending edge id
                    int key = eid[a]; int t = a - 1;
                    while (t >= 0 && eid[t] > key) { eid[t+1] = eid[t]; t--; }
                    eid[t+1] = key;
                }
                float s = v * 1e-3f;
                for (int k0 = 0; k0 < cnt; k0 += PF) {
                    int m = min(cnt - k0, PF);
                    int sk[PF]; float nx[PF], ny[PF], nz[PF];
                    #pragma unroll
                    for (int t = 0; t < PF; t++) {
                        if (t < m) {
                            int c = col[eid[k0 + t]];
                            g_csr[base + k0 + t] = c;   // rewrite own row (one line) with cols
                            sk[t] = (c == i);           // self-edge: exactly 0 contribution
                            nx[t] = orig[3*c]; ny[t] = orig[3*c+1]; nz[t] = orig[3*c+2];
                        } else sk[t] = 1;
                    }
                    pushPF(s, m, nx, ny, nz, sk, x, y, zz);
                }
            }
            g_pA[3*i] = x; g_pA[3*i+1] = y; g_pA[3*i+2] = zz;
        }
        sl[tid] = lloss;
        for (int d = ATHR/2; d > 0; d >>= 1) {
            __syncthreads();
            if (tid < d) sl[tid] += sl[tid + d];
        }
        __syncthreads();
        if (tid == 0) g_l1part[bid] = sl[0];
    }
    gbar(1, ABLK);

    // ---- sweeps 2 & 3 (rows < i read previous sweep's result; first-touch lines) ----
    #pragma unroll 1
    for (int sweep = 0; sweep < 2; sweep++) {
        const float* prev = (sweep == 0) ? g_pA : g_pB;
        float* outp       = (sweep == 0) ? g_pB : g_pA;
        int i = gtid;
        if (i < N) {
            float x = orig[3*i], y = orig[3*i+1], zz = orig[3*i+2];
            float v = g_viol[i];                 // own thread wrote it
            if (v > 0.0f) {
                int cnt = min(__ldcg(&g_cursor[i]), ROWCAP);
                float s = v * 1e-3f;
                int base = i * ROWCAP;
                for (int k0 = 0; k0 < cnt; k0 += PF) {
                    int m = min(cnt - k0, PF);
                    int sk[PF]; float nx[PF], ny[PF], nz[PF];
                    #pragma unroll
                    for (int t = 0; t < PF; t++) {
                        if (t < m) {
                            int c = g_csr[base + k0 + t];  // own row, own thread rewrote it
                            sk[t] = (c == i);
                            const float* pc = (c < i) ? prev : orig;
                            nx[t] = pc[3*c]; ny[t] = pc[3*c+1]; nz[t] = pc[3*c+2];
                        } else sk[t] = 1;
                    }
                    pushPF(s, m, nx, ny, nz, sk, x, y, zz);
                }
            }
            outp[3*i] = x; outp[3*i+1] = y; outp[3*i+2] = zz;
            if (sweep == 1) { g_pos2[3*i] = x; g_pos2[3*i+1] = y; g_pos2[3*i+2] = zz; }
        }
        if (sweep == 0) gbar(2, ABLK);
    }
}

// ===== kB: bond+cellcount | scan | cellfill (160 x 256, 2 grid barriers) ===========
__global__ void __launch_bounds__(BTHR) kB(const int* __restrict__ row,
                                           const int* __restrict__ col,
                                           const int* __restrict__ types,
                                           int N, int E) {
    __shared__ float sl[BTHR];
    __shared__ int   shi[BTHR];
    const int tid = threadIdx.x;
    const int bid = blockIdx.x;

    // ---- bond correction (blocks 0..127) + cell counts (blocks 128..159) ----
    if (bid < ABLK) {
        int e = bid * BTHR + tid;               // 128*256 = 32768 = E
        float l = 0.0f;
        if (e < E) {
            int r = row[e], c = col[e];
            float dx = g_pA[3*r]   - g_pA[3*c];
            float dy = g_pA[3*r+1] - g_pA[3*c+1];
            float dz = g_pA[3*r+2] - g_pA[3*c+2];
            float cur = sqrtf(dx*dx + dy*dy + dz*dz);
            float tgt = bond_of(types[r], types[c]);
            float df = cur - tgt;
            l = df * df;
            float ratio = fminf(fmaxf(tgt / (cur + 1e-8f), 0.98f), 1.02f);
            float sc = (ratio - 1.0f) * 0.005f;  // *0.01*0.5
            atomicAdd(&g_pos2[3*r],     dx * sc);
            atomicAdd(&g_pos2[3*r+1],   dy * sc);
            atomicAdd(&g_pos2[3*r+2],   dz * sc);
            atomicAdd(&g_pos2[3*c],    -dx * sc);
            atomicAdd(&g_pos2[3*c+1],  -dy * sc);
            atomicAdd(&g_pos2[3*c+2],  -dz * sc);
        }
        sl[tid] = l;
        for (int d = BTHR/2; d > 0; d >>= 1) {
            __syncthreads();
            if (tid < d) sl[tid] += sl[tid + d];
        }
        __syncthreads();
        if (tid == 0) g_l2part[bid] = sl[0];
    } else {
        int i = (bid - ABLK) * BTHR + tid;      // 32*256 = 8192 = N
        if (i < N)
            atomicAdd(&g_ccount[cell_of(g_pA[3*i], g_pA[3*i+1], g_pA[3*i+2])], 1);
    }
    gbar(3, BBLK);

    // ---- exclusive scan of cell counts (block 0, two-pass) ----
    if (bid == 0) {
        const int NI = (NCELL3 + BTHR - 1) / BTHR;   // 62
        int s = 0;
        for (int k = 0; k < NI; k++) {
            int idx = tid * NI + k;
            if (idx < NCELL3) s += __ldcg(&g_ccount[idx]);
        }
        shi[tid] = s;
        __syncthreads();
        for (int d = 1; d < BTHR; d <<= 1) {
            int v = (tid >= d) ? shi[tid - d] : 0;
            __syncthreads();
            shi[tid] += v;
            __syncthreads();
        }
        int run = shi[tid] - s;
        for (int k = 0; k < NI; k++) {
            int idx = tid * NI + k;
            if (idx < NCELL3) { g_coff[idx] = run; run += __ldcg(&g_ccount[idx]); }
        }
        if (tid == 0) g_coff[NCELL3] = shi[BTHR - 1];
    }
    gbar(4, BBLK);

    // ---- cell fill (first 32 blocks; first-touch reads of pos2/g_coff) ----
    if (bid < 32) {
        int i = bid * BTHR + tid;
        if (i < N) {
            int c = cell_of(g_pA[3*i], g_pA[3*i+1], g_pA[3*i+2]);  // identical binning
            int p = atomicAdd(&g_ccur[c], 1);
            int slot = __ldcg(&g_coff[c]) + p;
            g_catom[slot] = make_float4(__ldcg(&g_pos2[3*i]), __ldcg(&g_pos2[3*i+1]),
                                        __ldcg(&g_pos2[3*i+2]), g_rad8[i]);
            g_cidx[slot] = i;
        }
    }
}

// ===== kC: steric (warp-per-slot, 4x8 sub-warp rows) + finalize + resets ===========
__global__ void __launch_bounds__(256) kC(float* __restrict__ out, int N, int E,
                                          int nbS, int out_size) {
    __shared__ float sl[8];
    __shared__ float sh[256];
    __shared__ int   amLast;
    int tid  = threadIdx.x;
    int lane = tid & 31;
    int wid  = tid >> 5;
    int sub  = lane >> 3;                       // sub-warp 0..3 (8 lanes each)
    int lsub = lane & 7;
    int s = blockIdx.x * 8 + wid;               // slot (cell-ordered)
    float loss = 0.0f;
    if (s < N) {
        float4 me = g_catom[s];
        int i = g_cidx[s];
        int cx = cell_coord(me.x), cy = cell_coord(me.y), cz = cell_coord(me.z);
        int xlo = max(cx - 1, 0), xhi = min(cx + 1, NCELL - 1);
        float csum = 0.0f, cvx = 0.0f, cvy = 0.0f, cvz = 0.0f;
        // 3x3 (z,y) conceptual rows, distributed over 4 sub-warps; each row's
        // 3 x-cells are one contiguous slot range.
        for (int r = sub; r < 9; r += 4) {
            int z = cz - 1 + r / 3;
            int y = cy - 1 + r % 3;
            if (z < 0 || z >= NCELL || y < 0 || y >= NCELL) continue;
            int rowc = (z * NCELL + y) * NCELL;
            int kb = g_coff[rowc + xlo];
            int ke = g_coff[rowc + xhi + 1];
            for (int k = kb + lsub; k < ke; k += 8) {
                float4 q = g_catom[k];
                if (k == s) continue;           // exactly the i==j diagonal
                float dx = me.x - q.x, dy = me.y - q.y, dz = me.z - q.z;
                float d2 = dx*dx + dy*dy + dz*dz;
                float mind = me.w + q.w;
                if (d2 < mind * mind) {
                    float d2c = fmaxf(d2, 1e-20f);
                    float inv = rsqrtf(d2c);
                    float dist = d2c * inv;
                    float tt = mind - dist;
                    if (tt > 0.0f) {
                        loss += tt * tt;
                        if (dist > 1e-8f) {
                            float cc = tt * 0.0025f * inv;   // (mind-d)*0.005*0.5/d
                            csum += cc;
                            cvx += cc * q.x; cvy += cc * q.y; cvz += cc * q.z;
                        }
                    }
                }
            }
        }
        #pragma unroll
        for (int d = 16; d > 0; d >>= 1) {       // reduce across all 32 lanes
            csum += __shfl_xor_sync(0xffffffff, csum, d);
            cvx  += __shfl_xor_sync(0xffffffff, cvx,  d);
            cvy  += __shfl_xor_sync(0xffffffff, cvy,  d);
            cvz  += __shfl_xor_sync(0xffffffff, cvz,  d);
            loss += __shfl_xor_sync(0xffffffff, loss, d);
        }
        if (lane == 0) {
            out[3*i]   = me.x + csum * me.x - cvx;
            out[3*i+1] = me.y + csum * me.y - cvy;
            out[3*i+2] = me.z + csum * me.z - cvz;
        }
    }
    if (lane == 0) sl[wid] = loss;
    // reset all scratch counters + barriers for the next graph replay
    {
        int gs = gridDim.x * blockDim.x;
        int gt = blockIdx.x * blockDim.x + tid;
        for (int k = gt; k < N_MAX;  k += gs) g_cursor[k] = 0;
        for (int k = gt; k < NCELL3; k += gs) { g_ccount[k] = 0; g_ccur[k] = 0; }
        if (gt < 8) g_barc[gt] = 0;
    }
    __syncthreads();
    if (tid == 0) {
        float t = 0.0f;
        #pragma unroll
        for (int w = 0; w < 8; w++) t += sl[w];
        g_l3part[blockIdx.x] = t;
        __threadfence();
        amLast = (atomicAdd(&g_done, 1) == nbS - 1);
    }
    __syncthreads();
    // ---- last block: finalize loss (deterministic fixed-order sums) ----
    if (amLast) {
        float a = 0.0f;
        for (int k = tid; k < ABLK; k += 256)
            a += __ldcg(&g_l1part[k]) + __ldcg(&g_l2part[k]) / (float)E;
        for (int k = tid; k < nbS; k += 256)
            a += 0.5f * __ldcg(&g_l3part[k]);
        sh[tid] = a;
        for (int d = 128; d > 0; d >>= 1) {
            __syncthreads();
            if (tid < d) sh[tid] += sh[tid + d];
        }
        __syncthreads();
        if (tid == 0) { out[3*N] = sh[0] * 0.1f; g_done = 0; }
        for (int k = 3*N + 1 + tid; k < out_size; k += 256) out[k] = 0.0f;
    }
}

// ---------------- launcher: 3 kernels ----------------
extern "C" void kernel_launch(void* const* d_in, const int* in_sizes, int n_in,
                              void* d_out, int out_size) {
    const float* pos   = (const float*)d_in[0];
    const int*   edge  = (const int*)d_in[1];
    const int*   types = (const int*)d_in[2];
    float*       out   = (float*)d_out;

    int N = in_sizes[0] / 3;
    int E = in_sizes[1] / 2;
    const int* row = edge;
    const int* col = edge + E;

    int nbS = (N + 7) / 8;                  // 1024 steric blocks (warp per slot)

    kA<<<ABLK, ATHR>>>(pos, row, col, types, N, E);
    kB<<<BBLK, BTHR>>>(row, col, types, N, E);
    kC<<<nbS, 256>>>(out, N, E, nbS, out_size);
}

// round 17
// speedup vs baseline: 1.0890x; 1.0890x over previous
#include <cuda_runtime.h>
#include <math.h>

// Fixed problem shapes: N=8192 atoms, E=32768 edges (guarded for safety).
#define N_MAX   8192
#define E_MAX   32768
#define ROWCAP  32          // padded CSR row capacity; one row == one 128B cache line
#define NCELL   25
#define NCELL3  15625       // 25^3
#define CINV    0.3125f     // 1/3.2 ; cell 3.2 > max cutoff 3.168 + drift margin
#define CORG    40.0f
#define HOT_SPINS  100000000u  // hot-poll budget before backoff; never trips normally
#define ABLK    128
#define ATHR    64
#define BBLK    160         // 128 bond-blocks + 32 cellcount-blocks
#define BTHR    256
#define PF      16          // sweep prefetch width: one batch covers P(deg<=16) ~ 1

// ---------------- device scratch (zero-init; restored each run by kC) -------------
__device__ int    g_cursor[N_MAX];
__device__ int    g_csr[N_MAX * ROWCAP];    // edge ids; after sweep1 (violating rows): cols
__device__ float  g_viol[N_MAX];
__device__ float  g_rad8[N_MAX];
__device__ float  g_pA[N_MAX * 3];
__device__ float  g_pB[N_MAX * 3];
__device__ float  g_pos2[N_MAX * 3];
__device__ int    g_ccount[NCELL3];
__device__ int    g_ccur[NCELL3];
__device__ int    g_coff[NCELL3 + 1];
__device__ float4 g_catom[N_MAX];
__device__ int    g_cidx[N_MAX];
__device__ float  g_l1part[ABLK];
__device__ float  g_l2part[ABLK];
__device__ float  g_l3part[1024];
__device__ int    g_barc[8];                // spin-barrier counters (kA:0-2, kB:3-4)
__device__ int    g_done;                   // kC last-block ticket

// ---------------- chemistry as branchy constants ----------------
__device__ __forceinline__ float maxval_of(int z) {
    switch (z) {
        case 6:  return 4.f; case 7:  return 3.f; case 8:  return 2.f;
        case 16: return 6.f; case 15: return 5.f;
        case 9: case 17: case 35: case 53: case 1: return 1.f;
        default: return 4.f;
    }
}
__device__ __forceinline__ float vdw_of(int z) {
    switch (z) {
        case 1:  return 1.2f;  case 6:  return 1.7f;  case 7:  return 1.55f;
        case 8:  return 1.52f; case 9:  return 1.47f; case 15: return 1.8f;
        case 16: return 1.8f;  case 17: return 1.75f; case 35: return 1.85f;
        case 53: return 1.98f; default: return 1.6f;
    }
}
__device__ __forceinline__ float bond_of(int a, int b) {
    if (a > b) { int t = a; a = b; b = t; }
    switch (a * 64 + b) {
        case 1*64+6:  return 1.09f; case 1*64+7:  return 1.01f; case 1*64+8:  return 0.96f;
        case 6*64+6:  return 1.54f; case 6*64+7:  return 1.47f; case 6*64+8:  return 1.43f;
        case 6*64+9:  return 1.35f; case 6*64+16: return 1.82f; case 6*64+17: return 1.77f;
        case 7*64+7:  return 1.45f; case 7*64+8:  return 1.40f; case 8*64+8:  return 1.48f;
        case 8*64+15: return 1.63f; case 16*64+16: return 2.05f;
        default: return 1.5f;
    }
}
__device__ __forceinline__ int cell_coord(float v) {
    int c = (int)floorf((v + CORG) * CINV);
    return min(max(c, 0), NCELL - 1);
}
__device__ __forceinline__ int cell_of(float x, float y, float z) {
    return (cell_coord(z) * NCELL + cell_coord(y)) * NCELL + cell_coord(x);
}

// ---- grid barrier WITHOUT L1 invalidation ----------------------------------------
// __threadfence() emits CCTL.IVALL (L1D nuke) since fence scope >= cluster.
// Instead: release-atomic arrive (orders prior writes to L2) + relaxed poll.
// All genuinely cross-block reads after the barrier use __ldcg (L2 = coherence
// point), so warm L1 lines (read-only inputs, own-written rows) stay valid.
__device__ __forceinline__ void gbar(int idx, int nblk) {
    __syncthreads();
    if (threadIdx.x == 0) {
        int* p = &g_barc[idx];
        asm volatile("red.release.gpu.add.s32 [%0], 1;" :: "l"(p) : "memory");
        int v; unsigned spins = 0;
        while (true) {
            asm volatile("ld.relaxed.gpu.s32 %0, [%1];" : "=r"(v) : "l"(p) : "memory");
            if (v >= nblk) break;
            if (++spins > HOT_SPINS) {          // diagnostic tail; never trips normally
                __nanosleep(1000);
                if (spins > HOT_SPINS + 100000u) break;
            }
        }
    }
    __syncthreads();
}

// -------- fast push chain: prefetch PF neighbors, rsqrt math (validated 1.44e-7) ---
__device__ __forceinline__ void pushPF(float s, int m,
                                       const float* nx, const float* ny, const float* nz,
                                       const int* sk, float& x, float& y, float& z) {
    #pragma unroll
    for (int t = 0; t < PF; t++) {
        if (t < m && !sk[t]) {
            float dx = x - nx[t], dy = y - ny[t], dz = z - nz[t];
            float d2 = dx * dx + dy * dy + dz * dz;
            float f = s * rsqrtf(fmaxf(d2, 1e-24f));
            x += dx * f; y += dy * f; z += dz * f;
        }
    }
}

// ================= kA: fill + 3 Jacobi sweeps (128 x 64, 3 grid barriers) ==========
__global__ void __launch_bounds__(ATHR) kA(const float* __restrict__ orig,
                                           const int* __restrict__ row,
                                           const int* __restrict__ col,
                                           const int* __restrict__ types,
                                           int N, int E) {
    __shared__ float sl[ATHR];
    const int tid  = threadIdx.x;
    const int bid  = blockIdx.x;
    const int gtid = bid * ATHR + tid;          // == atom id in sweep phases
    const int GT   = ABLK * ATHR;               // 8192

    // ---- fill: padded CSR of edge ids (slot order irrelevant; sweep1 sorts) ----
    for (int e = gtid; e < E; e += GT) {
        int r = row[e];
        int p = atomicAdd(&g_cursor[r], 1);
        if (p < ROWCAP) g_csr[r * ROWCAP + p] = e;
    }
    gbar(0, ABLK);

    // ---- sweep 1: sort violating rows, viol/loss1/rad8, push ----
    {
        float lloss = 0.0f;
        int i = gtid;
        if (i < N) {
            int deg = __ldcg(&g_cursor[i]);      // cross-block atomics -> L2
            int cnt = min(deg, ROWCAP);
            int z = types[i];
            float v = fmaxf((float)deg - maxval_of(z), 0.0f);
            g_viol[i] = v;
            lloss = v * v;
            g_rad8[i] = vdw_of(z) * 0.8f;
            float x = orig[3*i], y = orig[3*i+1], zz = orig[3*i+2];
            if (v > 0.0f) {
                int base = i * ROWCAP;
                int eid[ROWCAP];
                for (int k = 0; k < cnt; k++) eid[k] = __ldcg(&g_csr[base + k]);
                for (int a = 1; a < cnt; a++) {  // stable = ascending edge id
                    int key = eid[a]; int t = a - 1;
                    while (t >= 0 && eid[t] > key) { eid[t+1] = eid[t]; t--; }
                    eid[t+1] = key;
                }
                float s = v * 1e-3f;
                for (int k0 = 0; k0 < cnt; k0 += PF) {
                    int m = min(cnt - k0, PF);
                    int sk[PF]; float nx[PF], ny[PF], nz[PF];
                    #pragma unroll
                    for (int t = 0; t < PF; t++) {
                        if (t < m) {
                            int c = col[eid[k0 + t]];
                            g_csr[base + k0 + t] = c;   // rewrite own row (one line) with cols
                            sk[t] = (c == i);           // self-edge: exactly 0 contribution
                            nx[t] = orig[3*c]; ny[t] = orig[3*c+1]; nz[t] = orig[3*c+2];
                        } else sk[t] = 1;
                    }
                    pushPF(s, m, nx, ny, nz, sk, x, y, zz);
                }
            }
            g_pA[3*i] = x; g_pA[3*i+1] = y; g_pA[3*i+2] = zz;
        }
        sl[tid] = lloss;
        for (int d = ATHR/2; d > 0; d >>= 1) {
            __syncthreads();
            if (tid < d) sl[tid] += sl[tid + d];
        }
        __syncthreads();
        if (tid == 0) g_l1part[bid] = sl[0];
    }
    gbar(1, ABLK);

    // ---- sweeps 2 & 3 (rows < i read previous sweep's result via __ldcg) ----
    #pragma unroll 1
    for (int sweep = 0; sweep < 2; sweep++) {
        const float* prev = (sweep == 0) ? g_pA : g_pB;
        float* outp       = (sweep == 0) ? g_pB : g_pA;
        int i = gtid;
        if (i < N) {
            float x = orig[3*i], y = orig[3*i+1], zz = orig[3*i+2];
            float v = g_viol[i];                 // own thread wrote it
            if (v > 0.0f) {
                int cnt = min(__ldcg(&g_cursor[i]), ROWCAP);
                float s = v * 1e-3f;
                int base = i * ROWCAP;
                for (int k0 = 0; k0 < cnt; k0 += PF) {
                    int m = min(cnt - k0, PF);
                    int sk[PF]; float nx[PF], ny[PF], nz[PF];
                    #pragma unroll
                    for (int t = 0; t < PF; t++) {
                        if (t < m) {
                            int c = g_csr[base + k0 + t];  // own row (L1-warm, own writes)
                            sk[t] = (c == i);
                            if (c < i) {                   // cross-block result -> L2
                                nx[t] = __ldcg(&prev[3*c]);
                                ny[t] = __ldcg(&prev[3*c+1]);
                                nz[t] = __ldcg(&prev[3*c+2]);
                            } else {                       // read-only input: L1-warm
                                nx[t] = orig[3*c]; ny[t] = orig[3*c+1]; nz[t] = orig[3*c+2];
                            }
                        } else sk[t] = 1;
                    }
                    pushPF(s, m, nx, ny, nz, sk, x, y, zz);
                }
            }
            outp[3*i] = x; outp[3*i+1] = y; outp[3*i+2] = zz;
            if (sweep == 1) { g_pos2[3*i] = x; g_pos2[3*i+1] = y; g_pos2[3*i+2] = zz; }
        }
        if (sweep == 0) gbar(2, ABLK);
    }
}

// ===== kB: bond+cellcount | scan | cellfill (160 x 256, 2 grid barriers) ===========
__global__ void __launch_bounds__(BTHR) kB(const int* __restrict__ row,
                                           const int* __restrict__ col,
                                           const int* __restrict__ types,
                                           int N, int E) {
    __shared__ float sl[BTHR];
    __shared__ int   shi[BTHR];
    const int tid = threadIdx.x;
    const int bid = blockIdx.x;

    // ---- bond correction (blocks 0..127) + cell counts (blocks 128..159) ----
    // g_pA was finalized in kA (separate launch -> L1 flushed): plain loads safe.
    if (bid < ABLK) {
        int e = bid * BTHR + tid;               // 128*256 = 32768 = E
        float l = 0.0f;
        if (e < E) {
            int r = row[e], c = col[e];
            float dx = g_pA[3*r]   - g_pA[3*c];
            float dy = g_pA[3*r+1] - g_pA[3*c+1];
            float dz = g_pA[3*r+2] - g_pA[3*c+2];
            float cur = sqrtf(dx*dx + dy*dy + dz*dz);
            float tgt = bond_of(types[r], types[c]);
            float df = cur - tgt;
            l = df * df;
            float ratio = fminf(fmaxf(tgt / (cur + 1e-8f), 0.98f), 1.02f);
            float sc = (ratio - 1.0f) * 0.005f;  // *0.01*0.5
            atomicAdd(&g_pos2[3*r],     dx * sc);
            atomicAdd(&g_pos2[3*r+1],   dy * sc);
            atomicAdd(&g_pos2[3*r+2],   dz * sc);
            atomicAdd(&g_pos2[3*c],    -dx * sc);
            atomicAdd(&g_pos2[3*c+1],  -dy * sc);
            atomicAdd(&g_pos2[3*c+2],  -dz * sc);
        }
        sl[tid] = l;
        for (int d = BTHR/2; d > 0; d >>= 1) {
            __syncthreads();
            if (tid < d) sl[tid] += sl[tid + d];
        }
        __syncthreads();
        if (tid == 0) g_l2part[bid] = sl[0];
    } else {
        int i = (bid - ABLK) * BTHR + tid;      // 32*256 = 8192 = N
        if (i < N)
            atomicAdd(&g_ccount[cell_of(g_pA[3*i], g_pA[3*i+1], g_pA[3*i+2])], 1);
    }
    gbar(3, BBLK);

    // ---- exclusive scan of cell counts (block 0, two-pass) ----
    if (bid == 0) {
        const int NI = (NCELL3 + BTHR - 1) / BTHR;   // 62
        int s = 0;
        for (int k = 0; k < NI; k++) {
            int idx = tid * NI + k;
            if (idx < NCELL3) s += __ldcg(&g_ccount[idx]);
        }
        shi[tid] = s;
        __syncthreads();
        for (int d = 1; d < BTHR; d <<= 1) {
            int v = (tid >= d) ? shi[tid - d] : 0;
            __syncthreads();
            shi[tid] += v;
            __syncthreads();
        }
        int run = shi[tid] - s;
        for (int k = 0; k < NI; k++) {
            int idx = tid * NI + k;
            if (idx < NCELL3) { g_coff[idx] = run; run += __ldcg(&g_ccount[idx]); }
        }
        if (tid == 0) g_coff[NCELL3] = shi[BTHR - 1];
    }
    gbar(4, BBLK);

    // ---- cell fill (first 32 blocks; cross-block data via __ldcg) ----
    if (bid < 32) {
        int i = bid * BTHR + tid;
        if (i < N) {
            int c = cell_of(g_pA[3*i], g_pA[3*i+1], g_pA[3*i+2]);  // identical binning
            int p = atomicAdd(&g_ccur[c], 1);
            int slot = __ldcg(&g_coff[c]) + p;
            g_catom[slot] = make_float4(__ldcg(&g_pos2[3*i]), __ldcg(&g_pos2[3*i+1]),
                                        __ldcg(&g_pos2[3*i+2]), g_rad8[i]);
            g_cidx[slot] = i;
        }
    }
}

// ===== kC: steric (warp-per-slot, 9 contiguous x-ranges) + finalize + resets =======
__global__ void __launch_bounds__(256) kC(float* __restrict__ out, int N, int E,
                                          int nbS, int out_size) {
    __shared__ float sl[8];
    __shared__ float sh[256];
    __shared__ int   amLast;
    int tid  = threadIdx.x;
    int lane = tid & 31;
    int wid  = tid >> 5;
    int s = blockIdx.x * 8 + wid;               // slot (cell-ordered)
    float loss = 0.0f;
    if (s < N) {
        float4 me = g_catom[s];
        int i = g_cidx[s];
        int cx = cell_coord(me.x), cy = cell_coord(me.y), cz = cell_coord(me.z);
        int xlo = max(cx - 1, 0), xhi = min(cx + 1, NCELL - 1);
        int ylo = max(cy - 1, 0), yhi = min(cy + 1, NCELL - 1);
        int zlo = max(cz - 1, 0), zhi = min(cz + 1, NCELL - 1);
        float csum = 0.0f, cvx = 0.0f, cvy = 0.0f, cvz = 0.0f;
        for (int z = zlo; z <= zhi; z++)
            for (int y = ylo; y <= yhi; y++) {
                int rowc = (z * NCELL + y) * NCELL;
                int kb = g_coff[rowc + xlo];
                int ke = g_coff[rowc + xhi + 1]; // x-neighbors are contiguous cells
                for (int k = kb + lane; k < ke; k += 32) {
                    float4 q = g_catom[k];
                    if (k == s) continue;        // exactly the i==j diagonal
                    float dx = me.x - q.x, dy = me.y - q.y, dz = me.z - q.z;
                    float d2 = dx*dx + dy*dy + dz*dz;
                    float mind = me.w + q.w;
                    if (d2 < mind * mind) {
                        float d2c = fmaxf(d2, 1e-20f);
                        float inv = rsqrtf(d2c);
                        float dist = d2c * inv;
                        float tt = mind - dist;
                        if (tt > 0.0f) {
                            loss += tt * tt;
                            if (dist > 1e-8f) {
                                float cc = tt * 0.0025f * inv;  // (mind-d)*0.005*0.5/d
                                csum += cc;
                                cvx += cc * q.x; cvy += cc * q.y; cvz += cc * q.z;
                            }
                        }
                    }
                }
            }
        #pragma unroll
        for (int d = 16; d > 0; d >>= 1) {
            csum += __shfl_xor_sync(0xffffffff, csum, d);
            cvx  += __shfl_xor_sync(0xffffffff, cvx,  d);
            cvy  += __shfl_xor_sync(0xffffffff, cvy,  d);
            cvz  += __shfl_xor_sync(0xffffffff, cvz,  d);
            loss += __shfl_xor_sync(0xffffffff, loss, d);
        }
        if (lane == 0) {
            out[3*i]   = me.x + csum * me.x - cvx;
            out[3*i+1] = me.y + csum * me.y - cvy;
            out[3*i+2] = me.z + csum * me.z - cvz;
        }
    }
    if (lane == 0) sl[wid] = loss;
    // reset all scratch counters + barriers for the next graph replay
    {
        int gs = gridDim.x * blockDim.x;
        int gt = blockIdx.x * blockDim.x + tid;
        for (int k = gt; k < N_MAX;  k += gs) g_cursor[k] = 0;
        for (int k = gt; k < NCELL3; k += gs) { g_ccount[k] = 0; g_ccur[k] = 0; }
        if (gt < 8) g_barc[gt] = 0;
    }
    __syncthreads();
    if (tid == 0) {
        float t = 0.0f;
        #pragma unroll
        for (int w = 0; w < 8; w++) t += sl[w];
        g_l3part[blockIdx.x] = t;
        __threadfence();
        amLast = (atomicAdd(&g_done, 1) == nbS - 1);
    }
    __syncthreads();
    // ---- last block: finalize loss (deterministic fixed-order sums) ----
    if (amLast) {
        float a = 0.0f;
        for (int k = tid; k < ABLK; k += 256)
            a += __ldcg(&g_l1part[k]) + __ldcg(&g_l2part[k]) / (float)E;
        for (int k = tid; k < nbS; k += 256)
            a += 0.5f * __ldcg(&g_l3part[k]);
        sh[tid] = a;
        for (int d = 128; d > 0; d >>= 1) {
            __syncthreads();
            if (tid < d) sh[tid] += sh[tid + d];
        }
        __syncthreads();
        if (tid == 0) { out[3*N] = sh[0] * 0.1f; g_done = 0; }
        for (int k = 3*N + 1 + tid; k < out_size; k += 256) out[k] = 0.0f;
    }
}

// ---------------- launcher: 3 kernels ----------------
extern "C" void kernel_launch(void* const* d_in, const int* in_sizes, int n_in,
                              void* d_out, int out_size) {
    const float* pos   = (const float*)d_in[0];
    const int*   edge  = (const int*)d_in[1];
    const int*   types = (const int*)d_in[2];
    float*       out   = (float*)d_out;

    int N = in_sizes[0] / 3;
    int E = in_sizes[1] / 2;
    const int* row = edge;
    const int* col = edge + E;

    int nbS = (N + 7) / 8;                  // 1024 steric blocks (warp per slot)

    kA<<<ABLK, ATHR>>>(pos, row, col, types, N, E);
    kB<<<BBLK, BTHR>>>(row, col, types, N, E);
    kC<<<nbS, 256>>>(out, N, E, nbS, out_size);
}